// round 13
// baseline (speedup 1.0000x reference)
#include <cuda_runtime.h>
#include <cuda_fp16.h>
#include <math.h>
#include <stdint.h>

// ---------------------------------------------------------------------------
// CausalSelfAttention (B=2,T=2048,C=1024,H=16,HD=64)
// R13: dense GEMMs: BK=64, 3-stage cp.async ring, ONE __syncthreads per
//      K-iteration (re-issue after top barrier is safe with 3 stages).
//      Same smem/SM budget -> occupancy unchanged (2 CTA/SM).
//      Flash = R9/R12 config (unchanged).
// ---------------------------------------------------------------------------

#define BATCH 2
#define SEQ   2048
#define CH    1024
#define NHEAD 16
#define HDIM  64
#define NROW  (BATCH * SEQ)

// ---------------- scratch ----------------
__device__ __half d_x16[NROW * CH];
__device__ __half d_a16[NROW * CH];
__device__ __half d_wa16T[3 * CH * CH];   // [N][K]
__device__ __half d_wp16T[CH * CH];
__device__ __half d_Q16[NROW * CH];
__device__ __half d_K16[NROW * CH];
__device__ __half d_V16[NROW * CH];

// ---------------- helpers ----------------
__device__ __forceinline__ uint32_t smem_u32(const void* p) {
    uint32_t a;
    asm("{ .reg .u64 t; cvta.to.shared.u64 t, %1; cvt.u32.u64 %0, t; }"
        : "=r"(a) : "l"(p));
    return a;
}

#define CP_ASYNC16(dst_u32, src_ptr) \
    asm volatile("cp.async.cg.shared.global [%0], [%1], 16;" \
                 :: "r"(dst_u32), "l"(src_ptr) : "memory")
#define CP_COMMIT() asm volatile("cp.async.commit_group;" ::: "memory")
#define CP_WAIT(n)  asm volatile("cp.async.wait_group %0;" :: "n"(n) : "memory")

__device__ __forceinline__ void mma_f16(float c[4], uint32_t a0, uint32_t a1,
                                        uint32_t a2, uint32_t a3,
                                        uint32_t b0, uint32_t b1) {
    asm volatile(
        "mma.sync.aligned.m16n8k16.row.col.f32.f16.f16.f32 "
        "{%0,%1,%2,%3}, {%4,%5,%6,%7}, {%8,%9}, {%0,%1,%2,%3};"
        : "+f"(c[0]), "+f"(c[1]), "+f"(c[2]), "+f"(c[3])
        : "r"(a0), "r"(a1), "r"(a2), "r"(a3), "r"(b0), "r"(b1));
}

__device__ __forceinline__ void ldsm4(uint32_t& r0, uint32_t& r1,
                                      uint32_t& r2, uint32_t& r3, uint32_t a) {
    asm volatile("ldmatrix.sync.aligned.m8n8.x4.shared.b16 {%0,%1,%2,%3}, [%4];"
                 : "=r"(r0), "=r"(r1), "=r"(r2), "=r"(r3) : "r"(a));
}

__device__ __forceinline__ void ldsm4t(uint32_t& r0, uint32_t& r1,
                                       uint32_t& r2, uint32_t& r3, uint32_t a) {
    asm volatile("ldmatrix.sync.aligned.m8n8.x4.trans.shared.b16 {%0,%1,%2,%3}, [%4];"
                 : "=r"(r0), "=r"(r1), "=r"(r2), "=r"(r3) : "r"(a));
}

__device__ __forceinline__ uint32_t pack2h(float a, float b) {
    __half2 h = __floats2half2_rn(a, b);
    return *(uint32_t*)&h;
}

// ---------------------------------------------------------------------------
// GEMM tile config: 128x128 CTA, 8 warps (warp 64x32), BK=64, 3-stage ring.
// Row = 64 fp16 (128B) + 16B pad = 144B -> conflict-free ldmatrix.
// ---------------------------------------------------------------------------
#define GM_BK 64
#define GM_ROWB 144
#define GM_BUFB (128 * GM_ROWB)            // 18432
#define GM_STAGEB (2 * GM_BUFB)            // 36864 (A+B)
#define GM_NSTAGE 3
#define GM_SMEM_BYTES (GM_NSTAGE * GM_STAGEB)   // 110592

struct GemmCore {
    uint32_t smb;
    int tid, wid, lid, wm, wn, m0, n0, K;
    const __half *A, *B;

    __device__ __forceinline__ void issue_stage(int st, int kt) {
        const uint32_t base = smb + (uint32_t)st * GM_STAGEB;
#pragma unroll
        for (int i = 0; i < 8; i++) {
            int id  = tid + i * 256;            // 0..2047
            int buf = id >> 10;                 // 0=A 1=B
            int cc  = id & 1023;
            int r   = cc >> 3;                  // 0..127
            int kc  = (cc & 7) * 8;             // fp16 col base 0..56
            uint32_t dst = base + (uint32_t)buf * GM_BUFB
                         + (uint32_t)(r * GM_ROWB + kc * 2);
            const __half* src = (buf == 0)
                ? A + (size_t)(m0 + r) * K + kt + kc
                : B + (size_t)(n0 + r) * K + kt + kc;
            CP_ASYNC16(dst, src);
        }
        CP_COMMIT();
    }

    __device__ __forceinline__ void run(float c[4][4][4]) {
        const int aRow = lid & 15;
        const int aCol = (lid >> 4) << 4;
        const int bRow = (lid & 7) + ((lid & 16) >> 1);
        const int bCol = ((lid >> 3) & 1) << 4;
        const int KT = K / GM_BK;               // 16 (>= 3)

        issue_stage(0, 0);
        issue_stage(1, GM_BK);
        issue_stage(2, 2 * GM_BK);

        for (int it = 0; it < KT; it++) {
            // ensure group 'it' has landed
            if (it == 0)              CP_WAIT(2);
            else if (it + 1 < KT)     CP_WAIT(1);
            else                      CP_WAIT(0);
            __syncthreads();

            // refill stage (it+2)%3 == (it-1)%3 (its reads completed at it-1)
            if (it >= 1 && it + 2 < KT)
                issue_stage((it + 2) % GM_NSTAGE, (it + 2) * GM_BK);

            const uint32_t stb = smb + (uint32_t)(it % GM_NSTAGE) * GM_STAGEB;

#pragma unroll
            for (int ks = 0; ks < GM_BK / 16; ks++) {
                const uint32_t kOff = (uint32_t)(ks * 32);
                uint32_t a[4][4];
#pragma unroll
                for (int mt = 0; mt < 4; mt++) {
                    uint32_t ra = stb + (uint32_t)((wm + mt * 16 + aRow) * GM_ROWB)
                                + kOff + aCol;
                    ldsm4(a[mt][0], a[mt][1], a[mt][2], a[mt][3], ra);
                }
                uint32_t b[4][2];
#pragma unroll
                for (int p = 0; p < 2; p++) {
                    uint32_t rb = stb + GM_BUFB
                                + (uint32_t)((wn + p * 16 + bRow) * GM_ROWB)
                                + kOff + bCol;
                    ldsm4(b[2*p][0], b[2*p][1], b[2*p+1][0], b[2*p+1][1], rb);
                }
#pragma unroll
                for (int nt = 0; nt < 4; nt++)
#pragma unroll
                    for (int mt = 0; mt < 4; mt++)
                        mma_f16(c[mt][nt], a[mt][0], a[mt][1], a[mt][2], a[mt][3],
                                b[nt][0], b[nt][1]);
            }
            // no tail barrier: next iteration's top barrier orders the refill
        }
    }
};

// ---------------------------------------------------------------------------
// QKV GEMM with fused bias + RoPE + head split epilogue -> fp16 Q/K/V
// ---------------------------------------------------------------------------
__global__ __launch_bounds__(256, 2)
void gemm_qkv(const __half* __restrict__ A,
              const __half* __restrict__ B,
              const float* __restrict__ bias,
              const float* __restrict__ cosT,
              const float* __restrict__ sinT)
{
    extern __shared__ char sm[];
    GemmCore gc;
    gc.smb = smem_u32(sm);
    gc.tid = threadIdx.x;
    gc.wid = gc.tid >> 5;
    gc.lid = gc.tid & 31;
    gc.wm  = (gc.wid >> 2) * 64;
    gc.wn  = (gc.wid & 3) * 32;
    gc.m0  = blockIdx.y * 128;
    gc.n0  = blockIdx.x * 128;
    gc.K   = CH;
    gc.A = A; gc.B = B;

    float c[4][4][4];
#pragma unroll
    for (int i = 0; i < 4; i++)
#pragma unroll
        for (int j = 0; j < 4; j++)
#pragma unroll
            for (int q = 0; q < 4; q++) c[i][j][q] = 0.f;

    gc.run(c);

    const int gid = gc.lid >> 2;
    const int tig = gc.lid & 3;

#pragma unroll
    for (int mt = 0; mt < 4; mt++) {
#pragma unroll
        for (int nt = 0; nt < 4; nt++) {
            const int col = gc.n0 + gc.wn + nt * 8 + tig * 2;
            float2 b01 = *(const float2*)(bias + col);
            const int seg = col >> 10;
            const int cc  = col & 1023;
            const int h   = cc >> 6;
            const int d   = cc & 63;
            const int pr  = d >> 1;
            __half* Dst = (seg == 0) ? d_Q16 : (seg == 1) ? d_K16 : d_V16;
#pragma unroll
            for (int half_ = 0; half_ < 2; half_++) {
                const int row = gc.m0 + gc.wm + mt * 16 + gid + half_ * 8;
                const int t   = row & (SEQ - 1);
                const int b   = row >> 11;
                float e = c[mt][nt][half_ * 2 + 0] + b01.x;
                float o = c[mt][nt][half_ * 2 + 1] + b01.y;
                if (seg < 2) {
                    float cs = cosT[t * 32 + pr];
                    float sn = sinT[t * 32 + pr];
                    float re = e * cs - o * sn;
                    float ro = e * sn + o * cs;
                    e = re; o = ro;
                }
                size_t off = ((size_t)(b * NHEAD + h) * SEQ + t) * HDIM + d;
                *(uint32_t*)(Dst + off) = pack2h(e, o);
            }
        }
    }
}

// ---------------------------------------------------------------------------
// projection GEMM: fp32 output + bias
// ---------------------------------------------------------------------------
__global__ __launch_bounds__(256, 2)
void gemm_proj(const __half* __restrict__ A,
               const __half* __restrict__ B,
               const float* __restrict__ bias, float* __restrict__ C,
               int M, int N, int K)
{
    extern __shared__ char sm[];
    GemmCore gc;
    gc.smb = smem_u32(sm);
    gc.tid = threadIdx.x;
    gc.wid = gc.tid >> 5;
    gc.lid = gc.tid & 31;
    gc.wm  = (gc.wid >> 2) * 64;
    gc.wn  = (gc.wid & 3) * 32;
    gc.m0  = blockIdx.y * 128;
    gc.n0  = blockIdx.x * 128;
    gc.K   = K;
    gc.A = A; gc.B = B;

    float c[4][4][4];
#pragma unroll
    for (int i = 0; i < 4; i++)
#pragma unroll
        for (int j = 0; j < 4; j++)
#pragma unroll
            for (int q = 0; q < 4; q++) c[i][j][q] = 0.f;

    gc.run(c);

    const int gid = gc.lid >> 2;
    const int tig = gc.lid & 3;
#pragma unroll
    for (int mt = 0; mt < 4; mt++) {
#pragma unroll
        for (int nt = 0; nt < 4; nt++) {
            const int row = gc.m0 + gc.wm + mt * 16 + gid;
            const int col = gc.n0 + gc.wn + nt * 8 + tig * 2;
            float2 b01 = *(const float2*)(bias + col);
            float2 v0 = make_float2(c[mt][nt][0] + b01.x, c[mt][nt][1] + b01.y);
            float2 v1 = make_float2(c[mt][nt][2] + b01.x, c[mt][nt][3] + b01.y);
            *(float2*)(C + (size_t)row * N + col)       = v0;
            *(float2*)(C + (size_t)(row + 8) * N + col) = v1;
        }
    }
}

// ---------------------------------------------------------------------------
// fp32 -> fp16 convert
// ---------------------------------------------------------------------------
__global__ void convert_half(const float* __restrict__ X,
                             __half* __restrict__ Y, int n)
{
    int i = (blockIdx.x * blockDim.x + threadIdx.x) * 4;
    if (i >= n) return;
    float4 v = *(const float4*)(X + i);
    uint32_t p0 = pack2h(v.x, v.y);
    uint32_t p1 = pack2h(v.z, v.w);
    *(uint32_t*)(Y + i)     = p0;
    *(uint32_t*)(Y + i + 2) = p1;
}

// ---------------------------------------------------------------------------
// transpose: W[K,N] fp32 -> T[N,K] fp16
// ---------------------------------------------------------------------------
__global__ void transpose_half(const float* __restrict__ W,
                               __half* __restrict__ T, int K, int N)
{
    __shared__ float tile[32][33];
    const int n0 = blockIdx.x * 32;
    const int k0 = blockIdx.y * 32;
    const int tx = threadIdx.x;
    const int ty = threadIdx.y;
#pragma unroll
    for (int i = 0; i < 32; i += 8)
        tile[ty + i][tx] = W[(size_t)(k0 + ty + i) * N + n0 + tx];
    __syncthreads();
#pragma unroll
    for (int i = 0; i < 32; i += 8)
        T[(size_t)(n0 + ty + i) * K + k0 + tx] = __float2half(tile[tx][ty + i]);
}

// ---------------------------------------------------------------------------
// Flash attention: 64 queries/CTA, 128 threads (R9/R12 config — unchanged).
// ---------------------------------------------------------------------------
#define FA_STRB 144
#define FA_TILEB (64 * FA_STRB)
#define FA_KVSTAGE (2 * FA_TILEB)
#define FA_SMEM_BYTES (FA_TILEB + 2 * FA_KVSTAGE)

__global__ __launch_bounds__(128)
void flash_mma(const __half* __restrict__ Q,
               const __half* __restrict__ Kg,
               const __half* __restrict__ Vg,
               __half* __restrict__ Aout)
{
    extern __shared__ char smem[];
    const uint32_t smb = smem_u32(smem);
    const int tid = threadIdx.x;
    const int wid = tid >> 5;
    const int lid = tid & 31;
    const int g   = lid >> 2;
    const int t   = lid & 3;
    const int wq  = wid * 16;
    const int qt  = gridDim.x - 1 - blockIdx.x;
    const int bh  = blockIdx.y;
    const int q0  = qt * 64;

    const int aRow = lid & 15;
    const int aCol = (lid >> 4) << 4;
    const int bRow = (lid & 7) + ((lid & 16) >> 1);
    const int bCol = ((lid >> 3) & 1) << 4;
    const int vRow = (lid & 7) + ((lid >> 3) & 1) * 8;
    const int vColH = (lid >> 4) * 8;

    const size_t base = (size_t)bh * SEQ * HDIM;
    const __half* Qb = Q  + base;
    const __half* Kb = Kg + base;
    const __half* Vb = Vg + base;

    auto issue_kv = [&](int st, int kt) {
#pragma unroll
        for (int i = 0; i < 8; i++) {
            int id  = tid + i * 128;
            int buf = id >> 9;
            int cc  = id & 511;
            int r   = cc >> 3;
            int c8  = (cc & 7) * 8;
            uint32_t dst = smb + FA_TILEB + (uint32_t)st * FA_KVSTAGE
                         + (uint32_t)buf * FA_TILEB
                         + (uint32_t)(r * FA_STRB + c8 * 2);
            const __half* src = (buf == 0)
                ? Kb + (size_t)(kt + r) * HDIM + c8
                : Vb + (size_t)(kt + r) * HDIM + c8;
            CP_ASYNC16(dst, src);
        }
        CP_COMMIT();
    };

    issue_kv(0, 0);

#pragma unroll
    for (int i = 0; i < 4; i++) {
        int id = tid + i * 128;
        int r  = id >> 3;
        int c8 = (id & 7) * 8;
        uint4 v = *(const uint4*)(Qb + (size_t)(q0 + r) * HDIM + c8);
        *(uint4*)(smem + r * FA_STRB + c8 * 2) = v;
    }

    float m0 = -INFINITY, m1 = -INFINITY, l0 = 0.f, l1 = 0.f;
    float oc[8][4];
#pragma unroll
    for (int nf = 0; nf < 8; nf++)
#pragma unroll
        for (int cidx = 0; cidx < 4; cidx++) oc[nf][cidx] = 0.f;

    for (int jt = 0; jt <= qt; jt++) {
        if (jt < qt) {
            issue_kv((jt + 1) & 1, (jt + 1) * 64);
            CP_WAIT(1);
        } else {
            CP_WAIT(0);
        }
        __syncthreads();

        const uint32_t kvb = smb + FA_TILEB + (uint32_t)(jt & 1) * FA_KVSTAGE;

        float sc[8][4];
#pragma unroll
        for (int nf = 0; nf < 8; nf++)
#pragma unroll
            for (int cidx = 0; cidx < 4; cidx++) sc[nf][cidx] = 0.f;

#pragma unroll
        for (int kc = 0; kc < 4; kc++) {
            const uint32_t kOff = (uint32_t)(kc * 32);
            uint32_t qf[4];
            uint32_t qa = smb + (uint32_t)((wq + aRow) * FA_STRB) + kOff + aCol;
            ldsm4(qf[0], qf[1], qf[2], qf[3], qa);
#pragma unroll
            for (int p = 0; p < 4; p++) {
                uint32_t ka = kvb + (uint32_t)((p * 16 + bRow) * FA_STRB)
                            + kOff + bCol;
                uint32_t k0_, k1_, k2_, k3_;
                ldsm4(k0_, k1_, k2_, k3_, ka);
                mma_f16(sc[2*p],   qf[0], qf[1], qf[2], qf[3], k0_, k1_);
                mma_f16(sc[2*p+1], qf[0], qf[1], qf[2], qf[3], k2_, k3_);
            }
        }

#pragma unroll
        for (int nf = 0; nf < 8; nf++)
#pragma unroll
            for (int cidx = 0; cidx < 4; cidx++) sc[nf][cidx] *= 0.125f;

        if (jt == qt) {
            const int qg0 = q0 + wq + g;
            const int qg1 = qg0 + 8;
#pragma unroll
            for (int nf = 0; nf < 8; nf++) {
                const int kb = q0 + nf * 8 + t * 2;
                if (kb     > qg0) sc[nf][0] = -INFINITY;
                if (kb + 1 > qg0) sc[nf][1] = -INFINITY;
                if (kb     > qg1) sc[nf][2] = -INFINITY;
                if (kb + 1 > qg1) sc[nf][3] = -INFINITY;
            }
        }

        float a0 = -INFINITY, a1 = -INFINITY;
#pragma unroll
        for (int nf = 0; nf < 8; nf++) {
            a0 = fmaxf(a0, fmaxf(sc[nf][0], sc[nf][1]));
            a1 = fmaxf(a1, fmaxf(sc[nf][2], sc[nf][3]));
        }
        a0 = fmaxf(a0, __shfl_xor_sync(0xffffffffu, a0, 1));
        a0 = fmaxf(a0, __shfl_xor_sync(0xffffffffu, a0, 2));
        a1 = fmaxf(a1, __shfl_xor_sync(0xffffffffu, a1, 1));
        a1 = fmaxf(a1, __shfl_xor_sync(0xffffffffu, a1, 2));

        float mn0 = fmaxf(m0, a0), mn1 = fmaxf(m1, a1);
        float cr0 = __expf(m0 - mn0), cr1 = __expf(m1 - mn1);
        float rs0 = 0.f, rs1 = 0.f;
#pragma unroll
        for (int nf = 0; nf < 8; nf++) {
            sc[nf][0] = __expf(sc[nf][0] - mn0);
            sc[nf][1] = __expf(sc[nf][1] - mn0);
            sc[nf][2] = __expf(sc[nf][2] - mn1);
            sc[nf][3] = __expf(sc[nf][3] - mn1);
            rs0 += sc[nf][0] + sc[nf][1];
            rs1 += sc[nf][2] + sc[nf][3];
        }
        rs0 += __shfl_xor_sync(0xffffffffu, rs0, 1);
        rs0 += __shfl_xor_sync(0xffffffffu, rs0, 2);
        rs1 += __shfl_xor_sync(0xffffffffu, rs1, 1);
        rs1 += __shfl_xor_sync(0xffffffffu, rs1, 2);
        l0 = l0 * cr0 + rs0;  m0 = mn0;
        l1 = l1 * cr1 + rs1;  m1 = mn1;
#pragma unroll
        for (int nf = 0; nf < 8; nf++) {
            oc[nf][0] *= cr0; oc[nf][1] *= cr0;
            oc[nf][2] *= cr1; oc[nf][3] *= cr1;
        }

#pragma unroll
        for (int kc = 0; kc < 4; kc++) {
            uint32_t pa0 = pack2h(sc[2*kc][0],   sc[2*kc][1]);
            uint32_t pa1 = pack2h(sc[2*kc][2],   sc[2*kc][3]);
            uint32_t pa2 = pack2h(sc[2*kc+1][0], sc[2*kc+1][1]);
            uint32_t pa3 = pack2h(sc[2*kc+1][2], sc[2*kc+1][3]);
#pragma unroll
            for (int p = 0; p < 4; p++) {
                uint32_t va = kvb + FA_TILEB
                            + (uint32_t)((kc * 16 + vRow) * FA_STRB)
                            + (uint32_t)((p * 16 + vColH) * 2);
                uint32_t v0, v1, v2, v3;
                ldsm4t(v0, v1, v2, v3, va);
                mma_f16(oc[2*p],   pa0, pa1, pa2, pa3, v0, v1);
                mma_f16(oc[2*p+1], pa0, pa1, pa2, pa3, v2, v3);
            }
        }
        __syncthreads();
    }

    const int b = bh >> 4;
    const int h = bh & 15;
    const float inv0 = 1.f / l0;
    const float inv1 = 1.f / l1;
    const int row0 = b * SEQ + q0 + wq + g;
    const int row1 = row0 + 8;
#pragma unroll
    for (int nf = 0; nf < 8; nf++) {
        const int col = h * HDIM + nf * 8 + t * 2;
        *(uint32_t*)(Aout + (size_t)row0 * CH + col) =
            pack2h(oc[nf][0] * inv0, oc[nf][1] * inv0);
        *(uint32_t*)(Aout + (size_t)row1 * CH + col) =
            pack2h(oc[nf][2] * inv1, oc[nf][3] * inv1);
    }
}

// ---------------------------------------------------------------------------
extern "C" void kernel_launch(void* const* d_in, const int* in_sizes, int n_in,
                              void* d_out, int out_size)
{
    const float* x      = (const float*)d_in[0];
    const float* cosT   = (const float*)d_in[1];
    const float* sinT   = (const float*)d_in[2];
    const float* w_attn = (const float*)d_in[3];
    const float* b_attn = (const float*)d_in[4];
    const float* w_proj = (const float*)d_in[5];
    const float* b_proj = (const float*)d_in[6];
    float* out = (float*)d_out;

    __half *x16, *a16, *wa16, *wp16, *q16, *k16, *v16;
    cudaGetSymbolAddress((void**)&x16,  d_x16);
    cudaGetSymbolAddress((void**)&a16,  d_a16);
    cudaGetSymbolAddress((void**)&wa16, d_wa16T);
    cudaGetSymbolAddress((void**)&wp16, d_wp16T);
    cudaGetSymbolAddress((void**)&q16,  d_Q16);
    cudaGetSymbolAddress((void**)&k16,  d_K16);
    cudaGetSymbolAddress((void**)&v16,  d_V16);

    cudaFuncSetAttribute(gemm_qkv, cudaFuncAttributeMaxDynamicSharedMemorySize,
                         GM_SMEM_BYTES);
    cudaFuncSetAttribute(gemm_proj, cudaFuncAttributeMaxDynamicSharedMemorySize,
                         GM_SMEM_BYTES);
    cudaFuncSetAttribute(flash_mma, cudaFuncAttributeMaxDynamicSharedMemorySize,
                         FA_SMEM_BYTES);

    {
        int n = NROW * CH;
        convert_half<<<(n / 4 + 255) / 256, 256>>>(x, x16, n);
        transpose_half<<<dim3(3 * CH / 32, CH / 32), dim3(32, 8)>>>(
            w_attn, wa16, CH, 3 * CH);
        transpose_half<<<dim3(CH / 32, CH / 32), dim3(32, 8)>>>(
            w_proj, wp16, CH, CH);
    }

    // 1) QKV GEMM with fused RoPE/split epilogue  [M=4096, N=3072]
    gemm_qkv<<<dim3(3 * CH / 128, NROW / 128), 256, GM_SMEM_BYTES>>>(
        x16, wa16, b_attn, cosT, sinT);

    // 2) flash attention (64 q/CTA) -> fp16 proj operand
    flash_mma<<<dim3(SEQ / 64, BATCH * NHEAD), 128, FA_SMEM_BYTES>>>(
        q16, k16, v16, a16);

    // 3) projection GEMM  [M=4096, N=1024]
    gemm_proj<<<dim3(CH / 128, NROW / 128), 256, GM_SMEM_BYTES>>>(
        a16, wp16, b_proj, out, NROW, CH, CH);
}

// round 15
// speedup vs baseline: 1.0277x; 1.0277x over previous
#include <cuda_runtime.h>
#include <cuda_fp16.h>
#include <math.h>
#include <stdint.h>

// ---------------------------------------------------------------------------
// CausalSelfAttention (B=2,T=2048,C=1024,H=16,HD=64)
// R14: GEMMs = exact R12 config (BK=64, 2-stage, 73.7KB smem — R13's 110KB
//      3-stage starved L1D and regressed). Flash: single barrier per key
//      tile (prefetch issued after top barrier targets the other stage) +
//      hoisted tile-invariant Q fragments.
// ---------------------------------------------------------------------------

#define BATCH 2
#define SEQ   2048
#define CH    1024
#define NHEAD 16
#define HDIM  64
#define NROW  (BATCH * SEQ)

// ---------------- scratch ----------------
__device__ __half d_x16[NROW * CH];
__device__ __half d_a16[NROW * CH];
__device__ __half d_wa16T[3 * CH * CH];   // [N][K]
__device__ __half d_wp16T[CH * CH];
__device__ __half d_Q16[NROW * CH];
__device__ __half d_K16[NROW * CH];
__device__ __half d_V16[NROW * CH];

// ---------------- helpers ----------------
__device__ __forceinline__ uint32_t smem_u32(const void* p) {
    uint32_t a;
    asm("{ .reg .u64 t; cvta.to.shared.u64 t, %1; cvt.u32.u64 %0, t; }"
        : "=r"(a) : "l"(p));
    return a;
}

#define CP_ASYNC16(dst_u32, src_ptr) \
    asm volatile("cp.async.cg.shared.global [%0], [%1], 16;" \
                 :: "r"(dst_u32), "l"(src_ptr) : "memory")
#define CP_COMMIT() asm volatile("cp.async.commit_group;" ::: "memory")
#define CP_WAIT(n)  asm volatile("cp.async.wait_group %0;" :: "n"(n) : "memory")

__device__ __forceinline__ void mma_f16(float c[4], uint32_t a0, uint32_t a1,
                                        uint32_t a2, uint32_t a3,
                                        uint32_t b0, uint32_t b1) {
    asm volatile(
        "mma.sync.aligned.m16n8k16.row.col.f32.f16.f16.f32 "
        "{%0,%1,%2,%3}, {%4,%5,%6,%7}, {%8,%9}, {%0,%1,%2,%3};"
        : "+f"(c[0]), "+f"(c[1]), "+f"(c[2]), "+f"(c[3])
        : "r"(a0), "r"(a1), "r"(a2), "r"(a3), "r"(b0), "r"(b1));
}

__device__ __forceinline__ void ldsm4(uint32_t& r0, uint32_t& r1,
                                      uint32_t& r2, uint32_t& r3, uint32_t a) {
    asm volatile("ldmatrix.sync.aligned.m8n8.x4.shared.b16 {%0,%1,%2,%3}, [%4];"
                 : "=r"(r0), "=r"(r1), "=r"(r2), "=r"(r3) : "r"(a));
}

__device__ __forceinline__ void ldsm4t(uint32_t& r0, uint32_t& r1,
                                       uint32_t& r2, uint32_t& r3, uint32_t a) {
    asm volatile("ldmatrix.sync.aligned.m8n8.x4.trans.shared.b16 {%0,%1,%2,%3}, [%4];"
                 : "=r"(r0), "=r"(r1), "=r"(r2), "=r"(r3) : "r"(a));
}

__device__ __forceinline__ uint32_t pack2h(float a, float b) {
    __half2 h = __floats2half2_rn(a, b);
    return *(uint32_t*)&h;
}

// ---------------------------------------------------------------------------
// GEMM tile config (R12 exact): 128x128 CTA, 8 warps (warp 64x32), BK=64,
// 2-stage. Row = 144B (128 data + 16 pad) -> conflict-free ldmatrix.
// ---------------------------------------------------------------------------
#define GM_BK 64
#define GM_ROWB 144
#define GM_BUFB (128 * GM_ROWB)            // 18432
#define GM_STAGEB (2 * GM_BUFB)            // 36864 (A+B)
#define GM_NSTAGE 2
#define GM_SMEM_BYTES (GM_NSTAGE * GM_STAGEB)   // 73728

struct GemmCore {
    uint32_t smb;
    int tid, wid, lid, wm, wn, m0, n0, K;
    const __half *A, *B;

    __device__ __forceinline__ void issue_stage(int st, int kt) {
        const uint32_t base = smb + (uint32_t)st * GM_STAGEB;
#pragma unroll
        for (int i = 0; i < 8; i++) {
            int id  = tid + i * 256;            // 0..2047
            int buf = id >> 10;                 // 0=A 1=B
            int cc  = id & 1023;
            int r   = cc >> 3;                  // 0..127
            int kc  = (cc & 7) * 8;             // fp16 col base 0..56
            uint32_t dst = base + (uint32_t)buf * GM_BUFB
                         + (uint32_t)(r * GM_ROWB + kc * 2);
            const __half* src = (buf == 0)
                ? A + (size_t)(m0 + r) * K + kt + kc
                : B + (size_t)(n0 + r) * K + kt + kc;
            CP_ASYNC16(dst, src);
        }
        CP_COMMIT();
    }

    __device__ __forceinline__ void run(float c[4][4][4]) {
        const int aRow = lid & 15;
        const int aCol = (lid >> 4) << 4;
        const int bRow = (lid & 7) + ((lid & 16) >> 1);
        const int bCol = ((lid >> 3) & 1) << 4;
        const int KT = K / GM_BK;               // 16

        issue_stage(0, 0);
        issue_stage(1, GM_BK);

        for (int it = 0; it < KT; it++) {
            if (it + 1 < KT) CP_WAIT(1); else CP_WAIT(0);
            __syncthreads();

            const uint32_t stb = smb + (uint32_t)(it & 1) * GM_STAGEB;

#pragma unroll
            for (int ks = 0; ks < GM_BK / 16; ks++) {
                const uint32_t kOff = (uint32_t)(ks * 32);
                uint32_t a[4][4];
#pragma unroll
                for (int mt = 0; mt < 4; mt++) {
                    uint32_t ra = stb + (uint32_t)((wm + mt * 16 + aRow) * GM_ROWB)
                                + kOff + aCol;
                    ldsm4(a[mt][0], a[mt][1], a[mt][2], a[mt][3], ra);
                }
                uint32_t b[4][2];
#pragma unroll
                for (int p = 0; p < 2; p++) {
                    uint32_t rb = stb + GM_BUFB
                                + (uint32_t)((wn + p * 16 + bRow) * GM_ROWB)
                                + kOff + bCol;
                    ldsm4(b[2*p][0], b[2*p][1], b[2*p+1][0], b[2*p+1][1], rb);
                }
#pragma unroll
                for (int nt = 0; nt < 4; nt++)
#pragma unroll
                    for (int mt = 0; mt < 4; mt++)
                        mma_f16(c[mt][nt], a[mt][0], a[mt][1], a[mt][2], a[mt][3],
                                b[nt][0], b[nt][1]);
            }

            if (it + 2 < KT) {
                __syncthreads();                 // protect stage (it&1) rewrite
                issue_stage(it & 1, (it + 2) * GM_BK);
            }
        }
    }
};

// ---------------------------------------------------------------------------
// QKV GEMM with fused bias + RoPE + head split epilogue -> fp16 Q/K/V
// ---------------------------------------------------------------------------
__global__ __launch_bounds__(256, 2)
void gemm_qkv(const __half* __restrict__ A,
              const __half* __restrict__ B,
              const float* __restrict__ bias,
              const float* __restrict__ cosT,
              const float* __restrict__ sinT)
{
    extern __shared__ char sm[];
    GemmCore gc;
    gc.smb = smem_u32(sm);
    gc.tid = threadIdx.x;
    gc.wid = gc.tid >> 5;
    gc.lid = gc.tid & 31;
    gc.wm  = (gc.wid >> 2) * 64;
    gc.wn  = (gc.wid & 3) * 32;
    gc.m0  = blockIdx.y * 128;
    gc.n0  = blockIdx.x * 128;
    gc.K   = CH;
    gc.A = A; gc.B = B;

    float c[4][4][4];
#pragma unroll
    for (int i = 0; i < 4; i++)
#pragma unroll
        for (int j = 0; j < 4; j++)
#pragma unroll
            for (int q = 0; q < 4; q++) c[i][j][q] = 0.f;

    gc.run(c);

    const int gid = gc.lid >> 2;
    const int tig = gc.lid & 3;

#pragma unroll
    for (int mt = 0; mt < 4; mt++) {
#pragma unroll
        for (int nt = 0; nt < 4; nt++) {
            const int col = gc.n0 + gc.wn + nt * 8 + tig * 2;
            float2 b01 = *(const float2*)(bias + col);
            const int seg = col >> 10;
            const int cc  = col & 1023;
            const int h   = cc >> 6;
            const int d   = cc & 63;
            const int pr  = d >> 1;
            __half* Dst = (seg == 0) ? d_Q16 : (seg == 1) ? d_K16 : d_V16;
#pragma unroll
            for (int half_ = 0; half_ < 2; half_++) {
                const int row = gc.m0 + gc.wm + mt * 16 + gid + half_ * 8;
                const int t   = row & (SEQ - 1);
                const int b   = row >> 11;
                float e = c[mt][nt][half_ * 2 + 0] + b01.x;
                float o = c[mt][nt][half_ * 2 + 1] + b01.y;
                if (seg < 2) {
                    float cs = cosT[t * 32 + pr];
                    float sn = sinT[t * 32 + pr];
                    float re = e * cs - o * sn;
                    float ro = e * sn + o * cs;
                    e = re; o = ro;
                }
                size_t off = ((size_t)(b * NHEAD + h) * SEQ + t) * HDIM + d;
                *(uint32_t*)(Dst + off) = pack2h(e, o);
            }
        }
    }
}

// ---------------------------------------------------------------------------
// projection GEMM: fp32 output + bias
// ---------------------------------------------------------------------------
__global__ __launch_bounds__(256, 2)
void gemm_proj(const __half* __restrict__ A,
               const __half* __restrict__ B,
               const float* __restrict__ bias, float* __restrict__ C,
               int M, int N, int K)
{
    extern __shared__ char sm[];
    GemmCore gc;
    gc.smb = smem_u32(sm);
    gc.tid = threadIdx.x;
    gc.wid = gc.tid >> 5;
    gc.lid = gc.tid & 31;
    gc.wm  = (gc.wid >> 2) * 64;
    gc.wn  = (gc.wid & 3) * 32;
    gc.m0  = blockIdx.y * 128;
    gc.n0  = blockIdx.x * 128;
    gc.K   = K;
    gc.A = A; gc.B = B;

    float c[4][4][4];
#pragma unroll
    for (int i = 0; i < 4; i++)
#pragma unroll
        for (int j = 0; j < 4; j++)
#pragma unroll
            for (int q = 0; q < 4; q++) c[i][j][q] = 0.f;

    gc.run(c);

    const int gid = gc.lid >> 2;
    const int tig = gc.lid & 3;
#pragma unroll
    for (int mt = 0; mt < 4; mt++) {
#pragma unroll
        for (int nt = 0; nt < 4; nt++) {
            const int row = gc.m0 + gc.wm + mt * 16 + gid;
            const int col = gc.n0 + gc.wn + nt * 8 + tig * 2;
            float2 b01 = *(const float2*)(bias + col);
            float2 v0 = make_float2(c[mt][nt][0] + b01.x, c[mt][nt][1] + b01.y);
            float2 v1 = make_float2(c[mt][nt][2] + b01.x, c[mt][nt][3] + b01.y);
            *(float2*)(C + (size_t)row * N + col)       = v0;
            *(float2*)(C + (size_t)(row + 8) * N + col) = v1;
        }
    }
}

// ---------------------------------------------------------------------------
// fp32 -> fp16 convert
// ---------------------------------------------------------------------------
__global__ void convert_half(const float* __restrict__ X,
                             __half* __restrict__ Y, int n)
{
    int i = (blockIdx.x * blockDim.x + threadIdx.x) * 4;
    if (i >= n) return;
    float4 v = *(const float4*)(X + i);
    uint32_t p0 = pack2h(v.x, v.y);
    uint32_t p1 = pack2h(v.z, v.w);
    *(uint32_t*)(Y + i)     = p0;
    *(uint32_t*)(Y + i + 2) = p1;
}

// ---------------------------------------------------------------------------
// transpose: W[K,N] fp32 -> T[N,K] fp16
// ---------------------------------------------------------------------------
__global__ void transpose_half(const float* __restrict__ W,
                               __half* __restrict__ T, int K, int N)
{
    __shared__ float tile[32][33];
    const int n0 = blockIdx.x * 32;
    const int k0 = blockIdx.y * 32;
    const int tx = threadIdx.x;
    const int ty = threadIdx.y;
#pragma unroll
    for (int i = 0; i < 32; i += 8)
        tile[ty + i][tx] = W[(size_t)(k0 + ty + i) * N + n0 + tx];
    __syncthreads();
#pragma unroll
    for (int i = 0; i < 32; i += 8)
        T[(size_t)(n0 + ty + i) * K + k0 + tx] = __float2half(tile[tx][ty + i]);
}

// ---------------------------------------------------------------------------
// Flash attention: 64 queries/CTA, 128 threads. Single barrier per key tile
// (prefetch issued after top barrier; targets the opposite stage).
// Q fragments hoisted out of the key loop (tile-invariant).
// ---------------------------------------------------------------------------
#define FA_STRB 144
#define FA_TILEB (64 * FA_STRB)
#define FA_KVSTAGE (2 * FA_TILEB)
#define FA_SMEM_BYTES (FA_TILEB + 2 * FA_KVSTAGE)

__global__ __launch_bounds__(128)
void flash_mma(const __half* __restrict__ Q,
               const __half* __restrict__ Kg,
               const __half* __restrict__ Vg,
               __half* __restrict__ Aout)
{
    extern __shared__ char smem[];
    const uint32_t smb = smem_u32(smem);
    const int tid = threadIdx.x;
    const int wid = tid >> 5;
    const int lid = tid & 31;
    const int g   = lid >> 2;
    const int t   = lid & 3;
    const int wq  = wid * 16;
    const int qt  = gridDim.x - 1 - blockIdx.x;
    const int bh  = blockIdx.y;
    const int q0  = qt * 64;

    const int aRow = lid & 15;
    const int aCol = (lid >> 4) << 4;
    const int bRow = (lid & 7) + ((lid & 16) >> 1);
    const int bCol = ((lid >> 3) & 1) << 4;
    const int vRow = (lid & 7) + ((lid >> 3) & 1) * 8;
    const int vColH = (lid >> 4) * 8;

    const size_t base = (size_t)bh * SEQ * HDIM;
    const __half* Qb = Q  + base;
    const __half* Kb = Kg + base;
    const __half* Vb = Vg + base;

    auto issue_kv = [&](int st, int kt) {
#pragma unroll
        for (int i = 0; i < 8; i++) {
            int id  = tid + i * 128;
            int buf = id >> 9;
            int cc  = id & 511;
            int r   = cc >> 3;
            int c8  = (cc & 7) * 8;
            uint32_t dst = smb + FA_TILEB + (uint32_t)st * FA_KVSTAGE
                         + (uint32_t)buf * FA_TILEB
                         + (uint32_t)(r * FA_STRB + c8 * 2);
            const __half* src = (buf == 0)
                ? Kb + (size_t)(kt + r) * HDIM + c8
                : Vb + (size_t)(kt + r) * HDIM + c8;
            CP_ASYNC16(dst, src);
        }
        CP_COMMIT();
    };

    issue_kv(0, 0);

    // Q tile -> smem
#pragma unroll
    for (int i = 0; i < 4; i++) {
        int id = tid + i * 128;
        int r  = id >> 3;
        int c8 = (id & 7) * 8;
        uint4 v = *(const uint4*)(Qb + (size_t)(q0 + r) * HDIM + c8);
        *(uint4*)(smem + r * FA_STRB + c8 * 2) = v;
    }
    __syncthreads();

    // hoist Q fragments (invariant across key tiles)
    uint32_t qf[4][4];
#pragma unroll
    for (int kc = 0; kc < 4; kc++) {
        uint32_t qa = smb + (uint32_t)((wq + aRow) * FA_STRB)
                    + (uint32_t)(kc * 32) + aCol;
        ldsm4(qf[kc][0], qf[kc][1], qf[kc][2], qf[kc][3], qa);
    }

    float m0 = -INFINITY, m1 = -INFINITY, l0 = 0.f, l1 = 0.f;
    float oc[8][4];
#pragma unroll
    for (int nf = 0; nf < 8; nf++)
#pragma unroll
        for (int cidx = 0; cidx < 4; cidx++) oc[nf][cidx] = 0.f;

    for (int jt = 0; jt <= qt; jt++) {
        CP_WAIT(0);                 // group jt landed (only one in flight)
        __syncthreads();            // all warps done with prior stage reads

        if (jt < qt)                // prefetch next tile into the OTHER stage
            issue_kv((jt + 1) & 1, (jt + 1) * 64);

        const uint32_t kvb = smb + FA_TILEB + (uint32_t)(jt & 1) * FA_KVSTAGE;

        // ---- S = Q @ K^T ----
        float sc[8][4];
#pragma unroll
        for (int nf = 0; nf < 8; nf++)
#pragma unroll
            for (int cidx = 0; cidx < 4; cidx++) sc[nf][cidx] = 0.f;

#pragma unroll
        for (int kc = 0; kc < 4; kc++) {
            const uint32_t kOff = (uint32_t)(kc * 32);
#pragma unroll
            for (int p = 0; p < 4; p++) {
                uint32_t ka = kvb + (uint32_t)((p * 16 + bRow) * FA_STRB)
                            + kOff + bCol;
                uint32_t k0_, k1_, k2_, k3_;
                ldsm4(k0_, k1_, k2_, k3_, ka);
                mma_f16(sc[2*p],   qf[kc][0], qf[kc][1], qf[kc][2], qf[kc][3], k0_, k1_);
                mma_f16(sc[2*p+1], qf[kc][0], qf[kc][1], qf[kc][2], qf[kc][3], k2_, k3_);
            }
        }

#pragma unroll
        for (int nf = 0; nf < 8; nf++)
#pragma unroll
            for (int cidx = 0; cidx < 4; cidx++) sc[nf][cidx] *= 0.125f;

        if (jt == qt) {
            const int qg0 = q0 + wq + g;
            const int qg1 = qg0 + 8;
#pragma unroll
            for (int nf = 0; nf < 8; nf++) {
                const int kb = q0 + nf * 8 + t * 2;
                if (kb     > qg0) sc[nf][0] = -INFINITY;
                if (kb + 1 > qg0) sc[nf][1] = -INFINITY;
                if (kb     > qg1) sc[nf][2] = -INFINITY;
                if (kb + 1 > qg1) sc[nf][3] = -INFINITY;
            }
        }

        // ---- online softmax ----
        float a0 = -INFINITY, a1 = -INFINITY;
#pragma unroll
        for (int nf = 0; nf < 8; nf++) {
            a0 = fmaxf(a0, fmaxf(sc[nf][0], sc[nf][1]));
            a1 = fmaxf(a1, fmaxf(sc[nf][2], sc[nf][3]));
        }
        a0 = fmaxf(a0, __shfl_xor_sync(0xffffffffu, a0, 1));
        a0 = fmaxf(a0, __shfl_xor_sync(0xffffffffu, a0, 2));
        a1 = fmaxf(a1, __shfl_xor_sync(0xffffffffu, a1, 1));
        a1 = fmaxf(a1, __shfl_xor_sync(0xffffffffu, a1, 2));

        float mn0 = fmaxf(m0, a0), mn1 = fmaxf(m1, a1);
        float cr0 = __expf(m0 - mn0), cr1 = __expf(m1 - mn1);
        float rs0 = 0.f, rs1 = 0.f;
#pragma unroll
        for (int nf = 0; nf < 8; nf++) {
            sc[nf][0] = __expf(sc[nf][0] - mn0);
            sc[nf][1] = __expf(sc[nf][1] - mn0);
            sc[nf][2] = __expf(sc[nf][2] - mn1);
            sc[nf][3] = __expf(sc[nf][3] - mn1);
            rs0 += sc[nf][0] + sc[nf][1];
            rs1 += sc[nf][2] + sc[nf][3];
        }
        rs0 += __shfl_xor_sync(0xffffffffu, rs0, 1);
        rs0 += __shfl_xor_sync(0xffffffffu, rs0, 2);
        rs1 += __shfl_xor_sync(0xffffffffu, rs1, 1);
        rs1 += __shfl_xor_sync(0xffffffffu, rs1, 2);
        l0 = l0 * cr0 + rs0;  m0 = mn0;
        l1 = l1 * cr1 + rs1;  m1 = mn1;
#pragma unroll
        for (int nf = 0; nf < 8; nf++) {
            oc[nf][0] *= cr0; oc[nf][1] *= cr0;
            oc[nf][2] *= cr1; oc[nf][3] *= cr1;
        }

        // ---- O += P @ V ----
#pragma unroll
        for (int kc = 0; kc < 4; kc++) {
            uint32_t pa0 = pack2h(sc[2*kc][0],   sc[2*kc][1]);
            uint32_t pa1 = pack2h(sc[2*kc][2],   sc[2*kc][3]);
            uint32_t pa2 = pack2h(sc[2*kc+1][0], sc[2*kc+1][1]);
            uint32_t pa3 = pack2h(sc[2*kc+1][2], sc[2*kc+1][3]);
#pragma unroll
            for (int p = 0; p < 4; p++) {
                uint32_t va = kvb + FA_TILEB
                            + (uint32_t)((kc * 16 + vRow) * FA_STRB)
                            + (uint32_t)((p * 16 + vColH) * 2);
                uint32_t v0, v1, v2, v3;
                ldsm4t(v0, v1, v2, v3, va);
                mma_f16(oc[2*p],   pa0, pa1, pa2, pa3, v0, v1);
                mma_f16(oc[2*p+1], pa0, pa1, pa2, pa3, v2, v3);
            }
        }
        // no bottom barrier: next iteration's top barrier orders stage reuse
    }

    const int b = bh >> 4;
    const int h = bh & 15;
    const float inv0 = 1.f / l0;
    const float inv1 = 1.f / l1;
    const int row0 = b * SEQ + q0 + wq + g;
    const int row1 = row0 + 8;
#pragma unroll
    for (int nf = 0; nf < 8; nf++) {
        const int col = h * HDIM + nf * 8 + t * 2;
        *(uint32_t*)(Aout + (size_t)row0 * CH + col) =
            pack2h(oc[nf][0] * inv0, oc[nf][1] * inv0);
        *(uint32_t*)(Aout + (size_t)row1 * CH + col) =
            pack2h(oc[nf][2] * inv1, oc[nf][3] * inv1);
    }
}

// ---------------------------------------------------------------------------
extern "C" void kernel_launch(void* const* d_in, const int* in_sizes, int n_in,
                              void* d_out, int out_size)
{
    const float* x      = (const float*)d_in[0];
    const float* cosT   = (const float*)d_in[1];
    const float* sinT   = (const float*)d_in[2];
    const float* w_attn = (const float*)d_in[3];
    const float* b_attn = (const float*)d_in[4];
    const float* w_proj = (const float*)d_in[5];
    const float* b_proj = (const float*)d_in[6];
    float* out = (float*)d_out;

    __half *x16, *a16, *wa16, *wp16, *q16, *k16, *v16;
    cudaGetSymbolAddress((void**)&x16,  d_x16);
    cudaGetSymbolAddress((void**)&a16,  d_a16);
    cudaGetSymbolAddress((void**)&wa16, d_wa16T);
    cudaGetSymbolAddress((void**)&wp16, d_wp16T);
    cudaGetSymbolAddress((void**)&q16,  d_Q16);
    cudaGetSymbolAddress((void**)&k16,  d_K16);
    cudaGetSymbolAddress((void**)&v16,  d_V16);

    cudaFuncSetAttribute(gemm_qkv, cudaFuncAttributeMaxDynamicSharedMemorySize,
                         GM_SMEM_BYTES);
    cudaFuncSetAttribute(gemm_proj, cudaFuncAttributeMaxDynamicSharedMemorySize,
                         GM_SMEM_BYTES);
    cudaFuncSetAttribute(flash_mma, cudaFuncAttributeMaxDynamicSharedMemorySize,
                         FA_SMEM_BYTES);

    {
        int n = NROW * CH;
        convert_half<<<(n / 4 + 255) / 256, 256>>>(x, x16, n);
        transpose_half<<<dim3(3 * CH / 32, CH / 32), dim3(32, 8)>>>(
            w_attn, wa16, CH, 3 * CH);
        transpose_half<<<dim3(CH / 32, CH / 32), dim3(32, 8)>>>(
            w_proj, wp16, CH, CH);
    }

    // 1) QKV GEMM with fused RoPE/split epilogue  [M=4096, N=3072]
    gemm_qkv<<<dim3(3 * CH / 128, NROW / 128), 256, GM_SMEM_BYTES>>>(
        x16, wa16, b_attn, cosT, sinT);

    // 2) flash attention (64 q/CTA) -> fp16 proj operand
    flash_mma<<<dim3(SEQ / 64, BATCH * NHEAD), 128, FA_SMEM_BYTES>>>(
        q16, k16, v16, a16);

    // 3) projection GEMM  [M=4096, N=1024]
    gemm_proj<<<dim3(CH / 128, NROW / 128), 256, GM_SMEM_BYTES>>>(
        a16, wp16, b_proj, out, NROW, CH, CH);
}

// round 16
// speedup vs baseline: 1.5685x; 1.5262x over previous
#include <cuda_runtime.h>
#include <cuda_fp16.h>
#include <math.h>
#include <stdint.h>

// ---------------------------------------------------------------------------
// CausalSelfAttention (B=2,T=2048,C=1024,H=16,HD=64)
// R16: best-known combo, re-benched (R13/R15 sessions showed a ~1.5x DVFS
//      slow state with identical SASS — noise control round).
//      GEMMs = R12 exact (BK=64, 2-stage, 73.7KB smem, warp 64x32).
//      Flash = single barrier per key tile + hoisted Q fragments (R15; was
//      ~8-10us better than R12 flash under equal-clock comparison).
//      Glue: the two weight transposes merged into one launch.
// ---------------------------------------------------------------------------

#define BATCH 2
#define SEQ   2048
#define CH    1024
#define NHEAD 16
#define HDIM  64
#define NROW  (BATCH * SEQ)

// ---------------- scratch ----------------
__device__ __half d_x16[NROW * CH];
__device__ __half d_a16[NROW * CH];
__device__ __half d_wa16T[3 * CH * CH];   // [N][K]
__device__ __half d_wp16T[CH * CH];
__device__ __half d_Q16[NROW * CH];
__device__ __half d_K16[NROW * CH];
__device__ __half d_V16[NROW * CH];

// ---------------- helpers ----------------
__device__ __forceinline__ uint32_t smem_u32(const void* p) {
    uint32_t a;
    asm("{ .reg .u64 t; cvta.to.shared.u64 t, %1; cvt.u32.u64 %0, t; }"
        : "=r"(a) : "l"(p));
    return a;
}

#define CP_ASYNC16(dst_u32, src_ptr) \
    asm volatile("cp.async.cg.shared.global [%0], [%1], 16;" \
                 :: "r"(dst_u32), "l"(src_ptr) : "memory")
#define CP_COMMIT() asm volatile("cp.async.commit_group;" ::: "memory")
#define CP_WAIT(n)  asm volatile("cp.async.wait_group %0;" :: "n"(n) : "memory")

__device__ __forceinline__ void mma_f16(float c[4], uint32_t a0, uint32_t a1,
                                        uint32_t a2, uint32_t a3,
                                        uint32_t b0, uint32_t b1) {
    asm volatile(
        "mma.sync.aligned.m16n8k16.row.col.f32.f16.f16.f32 "
        "{%0,%1,%2,%3}, {%4,%5,%6,%7}, {%8,%9}, {%0,%1,%2,%3};"
        : "+f"(c[0]), "+f"(c[1]), "+f"(c[2]), "+f"(c[3])
        : "r"(a0), "r"(a1), "r"(a2), "r"(a3), "r"(b0), "r"(b1));
}

__device__ __forceinline__ void ldsm4(uint32_t& r0, uint32_t& r1,
                                      uint32_t& r2, uint32_t& r3, uint32_t a) {
    asm volatile("ldmatrix.sync.aligned.m8n8.x4.shared.b16 {%0,%1,%2,%3}, [%4];"
                 : "=r"(r0), "=r"(r1), "=r"(r2), "=r"(r3) : "r"(a));
}

__device__ __forceinline__ void ldsm4t(uint32_t& r0, uint32_t& r1,
                                       uint32_t& r2, uint32_t& r3, uint32_t a) {
    asm volatile("ldmatrix.sync.aligned.m8n8.x4.trans.shared.b16 {%0,%1,%2,%3}, [%4];"
                 : "=r"(r0), "=r"(r1), "=r"(r2), "=r"(r3) : "r"(a));
}

__device__ __forceinline__ uint32_t pack2h(float a, float b) {
    __half2 h = __floats2half2_rn(a, b);
    return *(uint32_t*)&h;
}

// ---------------------------------------------------------------------------
// GEMM tile config (R12 exact): 128x128 CTA, 8 warps (warp 64x32), BK=64,
// 2-stage. Row = 144B (128 data + 16 pad) -> conflict-free ldmatrix.
// ---------------------------------------------------------------------------
#define GM_BK 64
#define GM_ROWB 144
#define GM_BUFB (128 * GM_ROWB)            // 18432
#define GM_STAGEB (2 * GM_BUFB)            // 36864 (A+B)
#define GM_NSTAGE 2
#define GM_SMEM_BYTES (GM_NSTAGE * GM_STAGEB)   // 73728

struct GemmCore {
    uint32_t smb;
    int tid, wid, lid, wm, wn, m0, n0, K;
    const __half *A, *B;

    __device__ __forceinline__ void issue_stage(int st, int kt) {
        const uint32_t base = smb + (uint32_t)st * GM_STAGEB;
#pragma unroll
        for (int i = 0; i < 8; i++) {
            int id  = tid + i * 256;            // 0..2047
            int buf = id >> 10;                 // 0=A 1=B
            int cc  = id & 1023;
            int r   = cc >> 3;                  // 0..127
            int kc  = (cc & 7) * 8;             // fp16 col base 0..56
            uint32_t dst = base + (uint32_t)buf * GM_BUFB
                         + (uint32_t)(r * GM_ROWB + kc * 2);
            const __half* src = (buf == 0)
                ? A + (size_t)(m0 + r) * K + kt + kc
                : B + (size_t)(n0 + r) * K + kt + kc;
            CP_ASYNC16(dst, src);
        }
        CP_COMMIT();
    }

    __device__ __forceinline__ void run(float c[4][4][4]) {
        const int aRow = lid & 15;
        const int aCol = (lid >> 4) << 4;
        const int bRow = (lid & 7) + ((lid & 16) >> 1);
        const int bCol = ((lid >> 3) & 1) << 4;
        const int KT = K / GM_BK;               // 16

        issue_stage(0, 0);
        issue_stage(1, GM_BK);

        for (int it = 0; it < KT; it++) {
            if (it + 1 < KT) CP_WAIT(1); else CP_WAIT(0);
            __syncthreads();

            const uint32_t stb = smb + (uint32_t)(it & 1) * GM_STAGEB;

#pragma unroll
            for (int ks = 0; ks < GM_BK / 16; ks++) {
                const uint32_t kOff = (uint32_t)(ks * 32);
                uint32_t a[4][4];
#pragma unroll
                for (int mt = 0; mt < 4; mt++) {
                    uint32_t ra = stb + (uint32_t)((wm + mt * 16 + aRow) * GM_ROWB)
                                + kOff + aCol;
                    ldsm4(a[mt][0], a[mt][1], a[mt][2], a[mt][3], ra);
                }
                uint32_t b[4][2];
#pragma unroll
                for (int p = 0; p < 2; p++) {
                    uint32_t rb = stb + GM_BUFB
                                + (uint32_t)((wn + p * 16 + bRow) * GM_ROWB)
                                + kOff + bCol;
                    ldsm4(b[2*p][0], b[2*p][1], b[2*p+1][0], b[2*p+1][1], rb);
                }
#pragma unroll
                for (int nt = 0; nt < 4; nt++)
#pragma unroll
                    for (int mt = 0; mt < 4; mt++)
                        mma_f16(c[mt][nt], a[mt][0], a[mt][1], a[mt][2], a[mt][3],
                                b[nt][0], b[nt][1]);
            }

            if (it + 2 < KT) {
                __syncthreads();                 // protect stage (it&1) rewrite
                issue_stage(it & 1, (it + 2) * GM_BK);
            }
        }
    }
};

// ---------------------------------------------------------------------------
// QKV GEMM with fused bias + RoPE + head split epilogue -> fp16 Q/K/V
// ---------------------------------------------------------------------------
__global__ __launch_bounds__(256, 2)
void gemm_qkv(const __half* __restrict__ A,
              const __half* __restrict__ B,
              const float* __restrict__ bias,
              const float* __restrict__ cosT,
              const float* __restrict__ sinT)
{
    extern __shared__ char sm[];
    GemmCore gc;
    gc.smb = smem_u32(sm);
    gc.tid = threadIdx.x;
    gc.wid = gc.tid >> 5;
    gc.lid = gc.tid & 31;
    gc.wm  = (gc.wid >> 2) * 64;
    gc.wn  = (gc.wid & 3) * 32;
    gc.m0  = blockIdx.y * 128;
    gc.n0  = blockIdx.x * 128;
    gc.K   = CH;
    gc.A = A; gc.B = B;

    float c[4][4][4];
#pragma unroll
    for (int i = 0; i < 4; i++)
#pragma unroll
        for (int j = 0; j < 4; j++)
#pragma unroll
            for (int q = 0; q < 4; q++) c[i][j][q] = 0.f;

    gc.run(c);

    const int gid = gc.lid >> 2;
    const int tig = gc.lid & 3;

#pragma unroll
    for (int mt = 0; mt < 4; mt++) {
#pragma unroll
        for (int nt = 0; nt < 4; nt++) {
            const int col = gc.n0 + gc.wn + nt * 8 + tig * 2;
            float2 b01 = *(const float2*)(bias + col);
            const int seg = col >> 10;
            const int cc  = col & 1023;
            const int h   = cc >> 6;
            const int d   = cc & 63;
            const int pr  = d >> 1;
            __half* Dst = (seg == 0) ? d_Q16 : (seg == 1) ? d_K16 : d_V16;
#pragma unroll
            for (int half_ = 0; half_ < 2; half_++) {
                const int row = gc.m0 + gc.wm + mt * 16 + gid + half_ * 8;
                const int t   = row & (SEQ - 1);
                const int b   = row >> 11;
                float e = c[mt][nt][half_ * 2 + 0] + b01.x;
                float o = c[mt][nt][half_ * 2 + 1] + b01.y;
                if (seg < 2) {
                    float cs = cosT[t * 32 + pr];
                    float sn = sinT[t * 32 + pr];
                    float re = e * cs - o * sn;
                    float ro = e * sn + o * cs;
                    e = re; o = ro;
                }
                size_t off = ((size_t)(b * NHEAD + h) * SEQ + t) * HDIM + d;
                *(uint32_t*)(Dst + off) = pack2h(e, o);
            }
        }
    }
}

// ---------------------------------------------------------------------------
// projection GEMM: fp32 output + bias
// ---------------------------------------------------------------------------
__global__ __launch_bounds__(256, 2)
void gemm_proj(const __half* __restrict__ A,
               const __half* __restrict__ B,
               const float* __restrict__ bias, float* __restrict__ C,
               int M, int N, int K)
{
    extern __shared__ char sm[];
    GemmCore gc;
    gc.smb = smem_u32(sm);
    gc.tid = threadIdx.x;
    gc.wid = gc.tid >> 5;
    gc.lid = gc.tid & 31;
    gc.wm  = (gc.wid >> 2) * 64;
    gc.wn  = (gc.wid & 3) * 32;
    gc.m0  = blockIdx.y * 128;
    gc.n0  = blockIdx.x * 128;
    gc.K   = K;
    gc.A = A; gc.B = B;

    float c[4][4][4];
#pragma unroll
    for (int i = 0; i < 4; i++)
#pragma unroll
        for (int j = 0; j < 4; j++)
#pragma unroll
            for (int q = 0; q < 4; q++) c[i][j][q] = 0.f;

    gc.run(c);

    const int gid = gc.lid >> 2;
    const int tig = gc.lid & 3;
#pragma unroll
    for (int mt = 0; mt < 4; mt++) {
#pragma unroll
        for (int nt = 0; nt < 4; nt++) {
            const int row = gc.m0 + gc.wm + mt * 16 + gid;
            const int col = gc.n0 + gc.wn + nt * 8 + tig * 2;
            float2 b01 = *(const float2*)(bias + col);
            float2 v0 = make_float2(c[mt][nt][0] + b01.x, c[mt][nt][1] + b01.y);
            float2 v1 = make_float2(c[mt][nt][2] + b01.x, c[mt][nt][3] + b01.y);
            *(float2*)(C + (size_t)row * N + col)       = v0;
            *(float2*)(C + (size_t)(row + 8) * N + col) = v1;
        }
    }
}

// ---------------------------------------------------------------------------
// fp32 -> fp16 convert
// ---------------------------------------------------------------------------
__global__ void convert_half(const float* __restrict__ X,
                             __half* __restrict__ Y, int n)
{
    int i = (blockIdx.x * blockDim.x + threadIdx.x) * 4;
    if (i >= n) return;
    float4 v = *(const float4*)(X + i);
    uint32_t p0 = pack2h(v.x, v.y);
    uint32_t p1 = pack2h(v.z, v.w);
    *(uint32_t*)(Y + i)     = p0;
    *(uint32_t*)(Y + i + 2) = p1;
}

// ---------------------------------------------------------------------------
// transpose both weights in ONE launch:
// blockIdx.x < 96: w_attn [1024,3072] -> d_wa16T ; else w_proj -> d_wp16T
// ---------------------------------------------------------------------------
__global__ void transpose_both(const float* __restrict__ Wa,
                               const float* __restrict__ Wp)
{
    __shared__ float tile[32][33];
    const bool isA = blockIdx.x < 96;
    const int  n0  = (isA ? blockIdx.x : blockIdx.x - 96) * 32;
    const int  k0  = blockIdx.y * 32;
    const int  N   = isA ? 3 * CH : CH;
    const float* W = isA ? Wa : Wp;
    __half* T      = isA ? d_wa16T : d_wp16T;
    const int tx = threadIdx.x;
    const int ty = threadIdx.y;
#pragma unroll
    for (int i = 0; i < 32; i += 8)
        tile[ty + i][tx] = W[(size_t)(k0 + ty + i) * N + n0 + tx];
    __syncthreads();
#pragma unroll
    for (int i = 0; i < 32; i += 8)
        T[(size_t)(n0 + ty + i) * CH + k0 + tx] = __float2half(tile[tx][ty + i]);
}

// ---------------------------------------------------------------------------
// Flash attention: 64 queries/CTA, 128 threads. Single barrier per key tile
// (prefetch after top barrier targets the other stage) + hoisted Q frags.
// ---------------------------------------------------------------------------
#define FA_STRB 144
#define FA_TILEB (64 * FA_STRB)
#define FA_KVSTAGE (2 * FA_TILEB)
#define FA_SMEM_BYTES (FA_TILEB + 2 * FA_KVSTAGE)

__global__ __launch_bounds__(128)
void flash_mma(const __half* __restrict__ Q,
               const __half* __restrict__ Kg,
               const __half* __restrict__ Vg,
               __half* __restrict__ Aout)
{
    extern __shared__ char smem[];
    const uint32_t smb = smem_u32(smem);
    const int tid = threadIdx.x;
    const int wid = tid >> 5;
    const int lid = tid & 31;
    const int g   = lid >> 2;
    const int t   = lid & 3;
    const int wq  = wid * 16;
    const int qt  = gridDim.x - 1 - blockIdx.x;
    const int bh  = blockIdx.y;
    const int q0  = qt * 64;

    const int aRow = lid & 15;
    const int aCol = (lid >> 4) << 4;
    const int bRow = (lid & 7) + ((lid & 16) >> 1);
    const int bCol = ((lid >> 3) & 1) << 4;
    const int vRow = (lid & 7) + ((lid >> 3) & 1) * 8;
    const int vColH = (lid >> 4) * 8;

    const size_t base = (size_t)bh * SEQ * HDIM;
    const __half* Qb = Q  + base;
    const __half* Kb = Kg + base;
    const __half* Vb = Vg + base;

    auto issue_kv = [&](int st, int kt) {
#pragma unroll
        for (int i = 0; i < 8; i++) {
            int id  = tid + i * 128;
            int buf = id >> 9;
            int cc  = id & 511;
            int r   = cc >> 3;
            int c8  = (cc & 7) * 8;
            uint32_t dst = smb + FA_TILEB + (uint32_t)st * FA_KVSTAGE
                         + (uint32_t)buf * FA_TILEB
                         + (uint32_t)(r * FA_STRB + c8 * 2);
            const __half* src = (buf == 0)
                ? Kb + (size_t)(kt + r) * HDIM + c8
                : Vb + (size_t)(kt + r) * HDIM + c8;
            CP_ASYNC16(dst, src);
        }
        CP_COMMIT();
    };

    issue_kv(0, 0);

    // Q tile -> smem
#pragma unroll
    for (int i = 0; i < 4; i++) {
        int id = tid + i * 128;
        int r  = id >> 3;
        int c8 = (id & 7) * 8;
        uint4 v = *(const uint4*)(Qb + (size_t)(q0 + r) * HDIM + c8);
        *(uint4*)(smem + r * FA_STRB + c8 * 2) = v;
    }
    __syncthreads();

    // hoist Q fragments (invariant across key tiles)
    uint32_t qf[4][4];
#pragma unroll
    for (int kc = 0; kc < 4; kc++) {
        uint32_t qa = smb + (uint32_t)((wq + aRow) * FA_STRB)
                    + (uint32_t)(kc * 32) + aCol;
        ldsm4(qf[kc][0], qf[kc][1], qf[kc][2], qf[kc][3], qa);
    }

    float m0 = -INFINITY, m1 = -INFINITY, l0 = 0.f, l1 = 0.f;
    float oc[8][4];
#pragma unroll
    for (int nf = 0; nf < 8; nf++)
#pragma unroll
        for (int cidx = 0; cidx < 4; cidx++) oc[nf][cidx] = 0.f;

    for (int jt = 0; jt <= qt; jt++) {
        CP_WAIT(0);                 // group jt landed
        __syncthreads();            // all warps done with prior stage reads

        if (jt < qt)                // prefetch next tile into the OTHER stage
            issue_kv((jt + 1) & 1, (jt + 1) * 64);

        const uint32_t kvb = smb + FA_TILEB + (uint32_t)(jt & 1) * FA_KVSTAGE;

        // ---- S = Q @ K^T ----
        float sc[8][4];
#pragma unroll
        for (int nf = 0; nf < 8; nf++)
#pragma unroll
            for (int cidx = 0; cidx < 4; cidx++) sc[nf][cidx] = 0.f;

#pragma unroll
        for (int kc = 0; kc < 4; kc++) {
            const uint32_t kOff = (uint32_t)(kc * 32);
#pragma unroll
            for (int p = 0; p < 4; p++) {
                uint32_t ka = kvb + (uint32_t)((p * 16 + bRow) * FA_STRB)
                            + kOff + bCol;
                uint32_t k0_, k1_, k2_, k3_;
                ldsm4(k0_, k1_, k2_, k3_, ka);
                mma_f16(sc[2*p],   qf[kc][0], qf[kc][1], qf[kc][2], qf[kc][3], k0_, k1_);
                mma_f16(sc[2*p+1], qf[kc][0], qf[kc][1], qf[kc][2], qf[kc][3], k2_, k3_);
            }
        }

#pragma unroll
        for (int nf = 0; nf < 8; nf++)
#pragma unroll
            for (int cidx = 0; cidx < 4; cidx++) sc[nf][cidx] *= 0.125f;

        if (jt == qt) {
            const int qg0 = q0 + wq + g;
            const int qg1 = qg0 + 8;
#pragma unroll
            for (int nf = 0; nf < 8; nf++) {
                const int kb = q0 + nf * 8 + t * 2;
                if (kb     > qg0) sc[nf][0] = -INFINITY;
                if (kb + 1 > qg0) sc[nf][1] = -INFINITY;
                if (kb     > qg1) sc[nf][2] = -INFINITY;
                if (kb + 1 > qg1) sc[nf][3] = -INFINITY;
            }
        }

        // ---- online softmax ----
        float a0 = -INFINITY, a1 = -INFINITY;
#pragma unroll
        for (int nf = 0; nf < 8; nf++) {
            a0 = fmaxf(a0, fmaxf(sc[nf][0], sc[nf][1]));
            a1 = fmaxf(a1, fmaxf(sc[nf][2], sc[nf][3]));
        }
        a0 = fmaxf(a0, __shfl_xor_sync(0xffffffffu, a0, 1));
        a0 = fmaxf(a0, __shfl_xor_sync(0xffffffffu, a0, 2));
        a1 = fmaxf(a1, __shfl_xor_sync(0xffffffffu, a1, 1));
        a1 = fmaxf(a1, __shfl_xor_sync(0xffffffffu, a1, 2));

        float mn0 = fmaxf(m0, a0), mn1 = fmaxf(m1, a1);
        float cr0 = __expf(m0 - mn0), cr1 = __expf(m1 - mn1);
        float rs0 = 0.f, rs1 = 0.f;
#pragma unroll
        for (int nf = 0; nf < 8; nf++) {
            sc[nf][0] = __expf(sc[nf][0] - mn0);
            sc[nf][1] = __expf(sc[nf][1] - mn0);
            sc[nf][2] = __expf(sc[nf][2] - mn1);
            sc[nf][3] = __expf(sc[nf][3] - mn1);
            rs0 += sc[nf][0] + sc[nf][1];
            rs1 += sc[nf][2] + sc[nf][3];
        }
        rs0 += __shfl_xor_sync(0xffffffffu, rs0, 1);
        rs0 += __shfl_xor_sync(0xffffffffu, rs0, 2);
        rs1 += __shfl_xor_sync(0xffffffffu, rs1, 1);
        rs1 += __shfl_xor_sync(0xffffffffu, rs1, 2);
        l0 = l0 * cr0 + rs0;  m0 = mn0;
        l1 = l1 * cr1 + rs1;  m1 = mn1;
#pragma unroll
        for (int nf = 0; nf < 8; nf++) {
            oc[nf][0] *= cr0; oc[nf][1] *= cr0;
            oc[nf][2] *= cr1; oc[nf][3] *= cr1;
        }

        // ---- O += P @ V ----
#pragma unroll
        for (int kc = 0; kc < 4; kc++) {
            uint32_t pa0 = pack2h(sc[2*kc][0],   sc[2*kc][1]);
            uint32_t pa1 = pack2h(sc[2*kc][2],   sc[2*kc][3]);
            uint32_t pa2 = pack2h(sc[2*kc+1][0], sc[2*kc+1][1]);
            uint32_t pa3 = pack2h(sc[2*kc+1][2], sc[2*kc+1][3]);
#pragma unroll
            for (int p = 0; p < 4; p++) {
                uint32_t va = kvb + FA_TILEB
                            + (uint32_t)((kc * 16 + vRow) * FA_STRB)
                            + (uint32_t)((p * 16 + vColH) * 2);
                uint32_t v0, v1, v2, v3;
                ldsm4t(v0, v1, v2, v3, va);
                mma_f16(oc[2*p],   pa0, pa1, pa2, pa3, v0, v1);
                mma_f16(oc[2*p+1], pa0, pa1, pa2, pa3, v2, v3);
            }
        }
        // no bottom barrier: next iteration's top barrier orders stage reuse
    }

    const int b = bh >> 4;
    const int h = bh & 15;
    const float inv0 = 1.f / l0;
    const float inv1 = 1.f / l1;
    const int row0 = b * SEQ + q0 + wq + g;
    const int row1 = row0 + 8;
#pragma unroll
    for (int nf = 0; nf < 8; nf++) {
        const int col = h * HDIM + nf * 8 + t * 2;
        *(uint32_t*)(Aout + (size_t)row0 * CH + col) =
            pack2h(oc[nf][0] * inv0, oc[nf][1] * inv0);
        *(uint32_t*)(Aout + (size_t)row1 * CH + col) =
            pack2h(oc[nf][2] * inv1, oc[nf][3] * inv1);
    }
}

// ---------------------------------------------------------------------------
extern "C" void kernel_launch(void* const* d_in, const int* in_sizes, int n_in,
                              void* d_out, int out_size)
{
    const float* x      = (const float*)d_in[0];
    const float* cosT   = (const float*)d_in[1];
    const float* sinT   = (const float*)d_in[2];
    const float* w_attn = (const float*)d_in[3];
    const float* b_attn = (const float*)d_in[4];
    const float* w_proj = (const float*)d_in[5];
    const float* b_proj = (const float*)d_in[6];
    float* out = (float*)d_out;

    __half *x16, *a16, *wa16, *wp16, *q16, *k16, *v16;
    cudaGetSymbolAddress((void**)&x16,  d_x16);
    cudaGetSymbolAddress((void**)&a16,  d_a16);
    cudaGetSymbolAddress((void**)&wa16, d_wa16T);
    cudaGetSymbolAddress((void**)&wp16, d_wp16T);
    cudaGetSymbolAddress((void**)&q16,  d_Q16);
    cudaGetSymbolAddress((void**)&k16,  d_K16);
    cudaGetSymbolAddress((void**)&v16,  d_V16);

    cudaFuncSetAttribute(gemm_qkv, cudaFuncAttributeMaxDynamicSharedMemorySize,
                         GM_SMEM_BYTES);
    cudaFuncSetAttribute(gemm_proj, cudaFuncAttributeMaxDynamicSharedMemorySize,
                         GM_SMEM_BYTES);
    cudaFuncSetAttribute(flash_mma, cudaFuncAttributeMaxDynamicSharedMemorySize,
                         FA_SMEM_BYTES);

    {
        int n = NROW * CH;
        convert_half<<<(n / 4 + 255) / 256, 256>>>(x, x16, n);
        transpose_both<<<dim3(128, CH / 32), dim3(32, 8)>>>(w_attn, w_proj);
    }

    // 1) QKV GEMM with fused RoPE/split epilogue  [M=4096, N=3072]
    gemm_qkv<<<dim3(3 * CH / 128, NROW / 128), 256, GM_SMEM_BYTES>>>(
        x16, wa16, b_attn, cosT, sinT);

    // 2) flash attention (64 q/CTA) -> fp16 proj operand
    flash_mma<<<dim3(SEQ / 64, BATCH * NHEAD), 128, FA_SMEM_BYTES>>>(
        q16, k16, v16, a16);

    // 3) projection GEMM  [M=4096, N=1024]
    gemm_proj<<<dim3(CH / 128, NROW / 128), 256, GM_SMEM_BYTES>>>(
        a16, wp16, b_proj, out, NROW, CH, CH);
}